// round 4
// baseline (speedup 1.0000x reference)
#include <cuda_runtime.h>
#include <cstdint>

#define N_DIM 2048
#define H_DIM 2048
#define V_DIM 32000

// ---- scratch ----
__device__ int8_t g_Wq[(size_t)V_DIM * H_DIM];   // 65 MB
__device__ int8_t g_xq[(size_t)N_DIM * H_DIM];   // 4 MB
__device__ float  g_sx[N_DIM];
__device__ float  g_sw[V_DIM];
__device__ double g_acc;

// ============================================================
// Kernel 1: per-row symmetric int8 quantization (one block per row)
// ============================================================
__global__ void __launch_bounds__(256)
quant_kernel(const float* __restrict__ src, int is_w) {
    const int row = blockIdx.x;
    const int tid = threadIdx.x;
    const int lane = tid & 31;
    const int warp = tid >> 5;

    if (is_w == 0 && row == 0 && tid == 0) g_acc = 0.0;

    const float4* s4 = (const float4*)(src + (size_t)row * H_DIM);
    float4 v0 = s4[tid];
    float4 v1 = s4[tid + 256];

    float m = fmaxf(fmaxf(fabsf(v0.x), fabsf(v0.y)),
                    fmaxf(fabsf(v0.z), fabsf(v0.w)));
    m = fmaxf(m, fmaxf(fmaxf(fabsf(v1.x), fabsf(v1.y)),
                       fmaxf(fabsf(v1.z), fabsf(v1.w))));
    #pragma unroll
    for (int off = 16; off; off >>= 1)
        m = fmaxf(m, __shfl_xor_sync(0xFFFFFFFFu, m, off));

    __shared__ float sm[8];
    __shared__ float s_inv;
    if (lane == 0) sm[warp] = m;
    __syncthreads();
    if (tid == 0) {
        float mm = sm[0];
        #pragma unroll
        for (int i = 1; i < 8; i++) mm = fmaxf(mm, sm[i]);
        mm = fmaxf(mm, 1e-20f);
        s_inv = 127.0f / mm;
        float scale = mm / 127.0f;
        if (is_w) g_sw[row] = scale; else g_sx[row] = scale;
    }
    __syncthreads();
    const float inv = s_inv;

    int8_t* dst = (is_w ? g_Wq : g_xq) + (size_t)row * H_DIM;
    char4 c0, c1;
    c0.x = (char)__float2int_rn(v0.x * inv);
    c0.y = (char)__float2int_rn(v0.y * inv);
    c0.z = (char)__float2int_rn(v0.z * inv);
    c0.w = (char)__float2int_rn(v0.w * inv);
    c1.x = (char)__float2int_rn(v1.x * inv);
    c1.y = (char)__float2int_rn(v1.y * inv);
    c1.z = (char)__float2int_rn(v1.z * inv);
    c1.w = (char)__float2int_rn(v1.w * inv);
    ((char4*)dst)[tid] = c0;
    ((char4*)dst)[tid + 256] = c1;
}

// ============================================================
// Kernel 2: int8 IMMA GEMM (m16n8k32) + fused (logit - y)^2 reduction
//   CTA tile 128x128, BK=128 int8; 8 warps (2 M x 4 N), warp tile 64x32
//   4-stage cp.async pipeline; NO min-blocks clause (needs ~200 regs)
// ============================================================
#define BM 128
#define BN 128
#define BKB 128                       // k-bytes (== int8 elems) per tile
#define NK (H_DIM / BKB)              // 16
#define STAGES 4
#define TILE_BYTES (BM * BKB)         // 16384
#define STAGE_BYTES (2 * TILE_BYTES)  // 32768 (A + B)
#define SMEM_BYTES (STAGES * STAGE_BYTES)  // 131072
#define THREADS 256

__device__ __forceinline__ void cp_async16(uint32_t smem_addr, const void* gptr) {
    asm volatile("cp.async.cg.shared.global [%0], [%1], 16;"
                 :: "r"(smem_addr), "l"(gptr));
}

__global__ void __launch_bounds__(THREADS)
gemm_mse_kernel(const float* __restrict__ y) {
    extern __shared__ __align__(1024) char smem[];
    __shared__ float red[8];

    const int tid = threadIdx.x;
    const int lane = tid & 31;
    const int warp = tid >> 5;
    const int warp_m = warp & 1;   // 0..1
    const int warp_n = warp >> 1;  // 0..3

    const uint32_t sbase = (uint32_t)__cvta_generic_to_shared(smem);

    const int n_blk = blockIdx.x * BM;
    const int v_blk = blockIdx.y * BN;
    const int8_t* gA = g_xq + (size_t)n_blk * H_DIM;
    const int8_t* gB = g_Wq + (size_t)v_blk * H_DIM;

    // loader: 4 x 16B chunks per thread per matrix per tile
    auto issue_tile = [&](int kt) {
        const uint32_t st = sbase + (kt % STAGES) * STAGE_BYTES;
        const int8_t* gAk = gA + kt * BKB;
        const int8_t* gBk = gB + kt * BKB;
        #pragma unroll
        for (int i = 0; i < 4; i++) {
            int chunk = i * THREADS + tid;   // 0..1023
            int row = chunk >> 3;            // 0..127
            int c16 = chunk & 7;             // 16B col
            uint32_t off = (uint32_t)(row * 128 + ((c16 ^ (row & 7)) * 16));
            cp_async16(st + off, gAk + (size_t)row * H_DIM + c16 * 16);
            cp_async16(st + TILE_BYTES + off, gBk + (size_t)row * H_DIM + c16 * 16);
        }
    };

    issue_tile(0);
    asm volatile("cp.async.commit_group;");
    issue_tile(1);
    asm volatile("cp.async.commit_group;");
    issue_tile(2);
    asm volatile("cp.async.commit_group;");

    int c[4][4][4];
    #pragma unroll
    for (int mi = 0; mi < 4; mi++)
        #pragma unroll
        for (int ni = 0; ni < 4; ni++)
            #pragma unroll
            for (int r = 0; r < 4; r++) c[mi][ni][r] = 0;

    const int a_row_base = warp_m * 64 + (lane & 15);
    const int a_kc_lane = lane >> 4;                       // 0/1 -> +16B
    const int b_row_base = warp_n * 32 + (lane & 7) + (((lane >> 3) & 1) << 3);
    const int b_kc_lane = lane >> 4;

    for (int kt = 0; kt < NK; kt++) {
        asm volatile("cp.async.wait_group 2;");
        __syncthreads();

        const uint32_t aBase = sbase + (kt % STAGES) * STAGE_BYTES;
        const uint32_t bBase = aBase + TILE_BYTES;

        #pragma unroll
        for (int ks = 0; ks < 4; ks++) {   // 4 x k32 per tile
            uint32_t a[4][4];
            #pragma unroll
            for (int mi = 0; mi < 4; mi++) {
                int row = a_row_base + mi * 16;
                int kc = ks * 2 + a_kc_lane;
                uint32_t addr = aBase + (uint32_t)(row * 128 + ((kc ^ (row & 7)) * 16));
                asm volatile(
                    "ldmatrix.sync.aligned.m8n8.x4.shared.b16 {%0,%1,%2,%3}, [%4];"
                    : "=r"(a[mi][0]), "=r"(a[mi][1]), "=r"(a[mi][2]), "=r"(a[mi][3])
                    : "r"(addr));
            }
            uint32_t b[2][4];
            #pragma unroll
            for (int p = 0; p < 2; p++) {
                int row = b_row_base + p * 16;
                int kc = ks * 2 + b_kc_lane;
                uint32_t addr = bBase + (uint32_t)(row * 128 + ((kc ^ (row & 7)) * 16));
                asm volatile(
                    "ldmatrix.sync.aligned.m8n8.x4.shared.b16 {%0,%1,%2,%3}, [%4];"
                    : "=r"(b[p][0]), "=r"(b[p][1]), "=r"(b[p][2]), "=r"(b[p][3])
                    : "r"(addr));
            }
            #pragma unroll
            for (int mi = 0; mi < 4; mi++) {
                #pragma unroll
                for (int ni = 0; ni < 4; ni++) {
                    int p = ni >> 1;
                    int q = ni & 1;
                    asm volatile(
                        "mma.sync.aligned.m16n8k32.row.col.s32.s8.s8.s32 "
                        "{%0,%1,%2,%3}, {%4,%5,%6,%7}, {%8,%9}, {%0,%1,%2,%3};"
                        : "+r"(c[mi][ni][0]), "+r"(c[mi][ni][1]),
                          "+r"(c[mi][ni][2]), "+r"(c[mi][ni][3])
                        : "r"(a[mi][0]), "r"(a[mi][1]), "r"(a[mi][2]), "r"(a[mi][3]),
                          "r"(b[p][q]), "r"(b[p][q + 2]));
                }
            }
        }

        if (kt + 3 < NK) issue_tile(kt + 3);
        asm volatile("cp.async.commit_group;");   // empty group near the tail is fine
    }

    // ---- epilogue: logits = c * sx[n] * sw[v]; (logit - y)^2 ----
    const int gr = lane >> 2;
    const int gc = (lane & 3) * 2;
    float acc = 0.0f;
    #pragma unroll
    for (int mi = 0; mi < 4; mi++) {
        int gn0 = n_blk + warp_m * 64 + mi * 16 + gr;
        float sx0 = g_sx[gn0];
        float sx8 = g_sx[gn0 + 8];
        #pragma unroll
        for (int ni = 0; ni < 4; ni++) {
            int gv = v_blk + warp_n * 32 + ni * 8 + gc;
            float2 sw2 = *(const float2*)(g_sw + gv);
            float2 y01 = *(const float2*)(y + (size_t)gn0 * V_DIM + gv);
            float2 y23 = *(const float2*)(y + (size_t)(gn0 + 8) * V_DIM + gv);
            float d0 = (float)c[mi][ni][0] * sx0 * sw2.x - y01.x;
            float d1 = (float)c[mi][ni][1] * sx0 * sw2.y - y01.y;
            float d2 = (float)c[mi][ni][2] * sx8 * sw2.x - y23.x;
            float d3 = (float)c[mi][ni][3] * sx8 * sw2.y - y23.y;
            acc += d0 * d0 + d1 * d1 + d2 * d2 + d3 * d3;
        }
    }
    #pragma unroll
    for (int off = 16; off; off >>= 1)
        acc += __shfl_xor_sync(0xFFFFFFFFu, acc, off);
    if (lane == 0) red[warp] = acc;
    __syncthreads();
    if (warp == 0) {
        float sv = (lane < 8) ? red[lane] : 0.0f;
        #pragma unroll
        for (int off = 4; off; off >>= 1)
            sv += __shfl_xor_sync(0xFFFFFFFFu, sv, off);
        if (lane == 0) atomicAdd(&g_acc, (double)sv);
    }
}

// ============================================================
// Kernel 3: finalize
// ============================================================
__global__ void finalize_kernel(float* out) {
    out[0] = (float)(g_acc / ((double)N_DIM * (double)V_DIM));
}

// ============================================================
extern "C" void kernel_launch(void* const* d_in, const int* in_sizes, int n_in,
                              void* d_out, int out_size) {
    (void)in_sizes; (void)n_in; (void)out_size;
    const float* x = (const float*)d_in[0];   // [N, H]
    const float* y = (const float*)d_in[1];   // [N, V]
    const float* W = (const float*)d_in[2];   // [V, H]
    float* out = (float*)d_out;

    static bool attr_set = false;
    if (!attr_set) {
        cudaFuncSetAttribute(gemm_mse_kernel,
                             cudaFuncAttributeMaxDynamicSharedMemorySize,
                             SMEM_BYTES);
        attr_set = true;
    }

    quant_kernel<<<N_DIM, 256>>>(x, 0);
    quant_kernel<<<V_DIM, 256>>>(W, 1);

    dim3 grid(N_DIM / BM, V_DIM / BN);  // (16, 250): x-fastest -> W stripe L2 reuse
    gemm_mse_kernel<<<grid, THREADS, SMEM_BYTES>>>(y);

    finalize_kernel<<<1, 1>>>(out);
}

// round 5
// speedup vs baseline: 2.5619x; 2.5619x over previous
#include <cuda_runtime.h>
#include <cuda_bf16.h>
#include <cstdint>

#define N_DIM 2048
#define H_DIM 2048
#define V_DIM 32000

// ---- scratch ----
__device__ __nv_bfloat16 g_Wb[(size_t)V_DIM * H_DIM];   // 131 MB
__device__ __nv_bfloat16 g_xb[(size_t)N_DIM * H_DIM];   // 8 MB
__device__ double g_acc;

// ============================================================
// Kernel 1: fp32 -> bf16 conversion; zero accumulator
// ============================================================
__global__ void convert_kernel(const float* __restrict__ x,
                               const float* __restrict__ W) {
    size_t tid = (size_t)blockIdx.x * blockDim.x + threadIdx.x;
    size_t stride = (size_t)gridDim.x * blockDim.x;
    if (tid == 0) g_acc = 0.0;

    const size_t nW4 = (size_t)V_DIM * H_DIM / 4;
    const float4* W4 = (const float4*)W;
    for (size_t i = tid; i < nW4; i += stride) {
        float4 v = W4[i];
        __nv_bfloat162* dst = (__nv_bfloat162*)(g_Wb + i * 4);
        dst[0] = __floats2bfloat162_rn(v.x, v.y);
        dst[1] = __floats2bfloat162_rn(v.z, v.w);
    }
    const size_t nx4 = (size_t)N_DIM * H_DIM / 4;
    const float4* x4 = (const float4*)x;
    for (size_t i = tid; i < nx4; i += stride) {
        float4 v = x4[i];
        __nv_bfloat162* dst = (__nv_bfloat162*)(g_xb + i * 4);
        dst[0] = __floats2bfloat162_rn(v.x, v.y);
        dst[1] = __floats2bfloat162_rn(v.z, v.w);
    }
}

// ============================================================
// Kernel 2: bf16 HMMA GEMM + fused (logit - y)^2 reduction
//   CTA tile 256x128, BK=64; 8 warps (4 M x 2 N), warp tile 64x64
//   3-stage cp.async, one __syncthreads per k-tile
// ============================================================
#define BM 256
#define BN 128
#define BK 64
#define NK (H_DIM / BK)               // 32
#define STAGES 3
#define A_BYTES (BM * BK * 2)         // 32768
#define B_BYTES (BN * BK * 2)         // 16384
#define STAGE_BYTES (A_BYTES + B_BYTES)    // 49152
#define SMEM_BYTES (STAGES * STAGE_BYTES)  // 147456
#define THREADS 256

__device__ __forceinline__ void cp_async16(uint32_t smem_addr, const void* gptr) {
    asm volatile("cp.async.cg.shared.global [%0], [%1], 16;"
                 :: "r"(smem_addr), "l"(gptr));
}

__global__ void __launch_bounds__(THREADS)
gemm_mse_kernel(const float* __restrict__ y) {
    extern __shared__ __align__(1024) char smem[];
    __shared__ float red[8];

    const int tid = threadIdx.x;
    const int lane = tid & 31;
    const int warp = tid >> 5;
    const int warp_m = warp & 3;   // 0..3 -> 64-row slabs
    const int warp_n = warp >> 2;  // 0..1 -> 64-col slabs

    const uint32_t sbase = (uint32_t)__cvta_generic_to_shared(smem);

    const int n_blk = blockIdx.x * BM;
    const int v_blk = blockIdx.y * BN;
    const __nv_bfloat16* gA = g_xb + (size_t)n_blk * H_DIM;
    const __nv_bfloat16* gB = g_Wb + (size_t)v_blk * H_DIM;

    // loader: A = 2048 chunks of 16B (8/thread), B = 1024 chunks (4/thread)
    auto issue_tile = [&](int kt) {
        const uint32_t st = sbase + (kt % STAGES) * STAGE_BYTES;
        const __nv_bfloat16* gAk = gA + kt * BK;
        const __nv_bfloat16* gBk = gB + kt * BK;
        #pragma unroll
        for (int i = 0; i < 8; i++) {
            int chunk = i * THREADS + tid;   // 0..2047
            int row = chunk >> 3;            // 0..255
            int c16 = chunk & 7;
            uint32_t off = (uint32_t)(row * 128 + ((c16 ^ (row & 7)) * 16));
            cp_async16(st + off, gAk + (size_t)row * H_DIM + c16 * 8);
        }
        #pragma unroll
        for (int i = 0; i < 4; i++) {
            int chunk = i * THREADS + tid;   // 0..1023
            int row = chunk >> 3;            // 0..127
            int c16 = chunk & 7;
            uint32_t off = (uint32_t)(row * 128 + ((c16 ^ (row & 7)) * 16));
            cp_async16(st + A_BYTES + off, gBk + (size_t)row * H_DIM + c16 * 8);
        }
    };

    issue_tile(0);
    asm volatile("cp.async.commit_group;");
    issue_tile(1);
    asm volatile("cp.async.commit_group;");

    float c[4][8][4];
    #pragma unroll
    for (int mi = 0; mi < 4; mi++)
        #pragma unroll
        for (int ni = 0; ni < 8; ni++)
            #pragma unroll
            for (int r = 0; r < 4; r++) c[mi][ni][r] = 0.0f;

    // ldmatrix addressing (validated in round 1)
    const int a_row_base = warp_m * 64 + (lane & 15);
    const int a_kc_lane = lane >> 4;                  // 0/1
    const int b_row_base = warp_n * 64 + (lane & 7) + ((lane >> 4) << 3);
    const int b_kc_lane = (lane >> 3) & 1;

    for (int kt = 0; kt < NK; kt++) {
        asm volatile("cp.async.wait_group 1;");
        __syncthreads();

        const uint32_t aBase = sbase + (kt % STAGES) * STAGE_BYTES;
        const uint32_t bBase = aBase + A_BYTES;

        #pragma unroll
        for (int ks = 0; ks < 4; ks++) {   // 4 x k16 per tile
            uint32_t a[4][4];
            #pragma unroll
            for (int mi = 0; mi < 4; mi++) {
                int row = a_row_base + mi * 16;
                int kc = ks * 2 + a_kc_lane;
                uint32_t addr = aBase + (uint32_t)(row * 128 + ((kc ^ (row & 7)) * 16));
                asm volatile(
                    "ldmatrix.sync.aligned.m8n8.x4.shared.b16 {%0,%1,%2,%3}, [%4];"
                    : "=r"(a[mi][0]), "=r"(a[mi][1]), "=r"(a[mi][2]), "=r"(a[mi][3])
                    : "r"(addr));
            }
            uint32_t b[4][4];
            #pragma unroll
            for (int p = 0; p < 4; p++) {
                int row = b_row_base + p * 16;
                int kc = ks * 2 + b_kc_lane;
                uint32_t addr = bBase + (uint32_t)(row * 128 + ((kc ^ (row & 7)) * 16));
                asm volatile(
                    "ldmatrix.sync.aligned.m8n8.x4.shared.b16 {%0,%1,%2,%3}, [%4];"
                    : "=r"(b[p][0]), "=r"(b[p][1]), "=r"(b[p][2]), "=r"(b[p][3])
                    : "r"(addr));
            }
            #pragma unroll
            for (int mi = 0; mi < 4; mi++) {
                #pragma unroll
                for (int ni = 0; ni < 8; ni++) {
                    int p = ni >> 1;
                    int o = (ni & 1) * 2;
                    asm volatile(
                        "mma.sync.aligned.m16n8k16.row.col.f32.bf16.bf16.f32 "
                        "{%0,%1,%2,%3}, {%4,%5,%6,%7}, {%8,%9}, {%0,%1,%2,%3};"
                        : "+f"(c[mi][ni][0]), "+f"(c[mi][ni][1]),
                          "+f"(c[mi][ni][2]), "+f"(c[mi][ni][3])
                        : "r"(a[mi][0]), "r"(a[mi][1]), "r"(a[mi][2]), "r"(a[mi][3]),
                          "r"(b[p][o]), "r"(b[p][o + 1]));
                }
            }
        }

        if (kt + 2 < NK) issue_tile(kt + 2);
        asm volatile("cp.async.commit_group;");
    }

    // ---- epilogue: (logit - y)^2 ----
    const int gr = lane >> 2;
    const int gc = (lane & 3) * 2;
    float acc = 0.0f;
    #pragma unroll
    for (int mi = 0; mi < 4; mi++) {
        int gn0 = n_blk + warp_m * 64 + mi * 16 + gr;
        const float* y0 = y + (size_t)gn0 * V_DIM + v_blk;
        const float* y8 = y0 + (size_t)8 * V_DIM;
        #pragma unroll
        for (int ni = 0; ni < 8; ni++) {
            int col = warp_n * 64 + ni * 8 + gc;
            float2 y01 = *(const float2*)(y0 + col);
            float2 y23 = *(const float2*)(y8 + col);
            float d0 = c[mi][ni][0] - y01.x;
            float d1 = c[mi][ni][1] - y01.y;
            float d2 = c[mi][ni][2] - y23.x;
            float d3 = c[mi][ni][3] - y23.y;
            acc += d0 * d0 + d1 * d1 + d2 * d2 + d3 * d3;
        }
    }
    #pragma unroll
    for (int off = 16; off; off >>= 1)
        acc += __shfl_xor_sync(0xFFFFFFFFu, acc, off);
    if (lane == 0) red[warp] = acc;
    __syncthreads();
    if (warp == 0) {
        float sv = (lane < 8) ? red[lane] : 0.0f;
        #pragma unroll
        for (int off = 4; off; off >>= 1)
            sv += __shfl_xor_sync(0xFFFFFFFFu, sv, off);
        if (lane == 0) atomicAdd(&g_acc, (double)sv);
    }
}

// ============================================================
// Kernel 3: finalize
// ============================================================
__global__ void finalize_kernel(float* out) {
    out[0] = (float)(g_acc / ((double)N_DIM * (double)V_DIM));
}

// ============================================================
extern "C" void kernel_launch(void* const* d_in, const int* in_sizes, int n_in,
                              void* d_out, int out_size) {
    (void)in_sizes; (void)n_in; (void)out_size;
    const float* x = (const float*)d_in[0];   // [N, H]
    const float* y = (const float*)d_in[1];   // [N, V]
    const float* W = (const float*)d_in[2];   // [V, H]
    float* out = (float*)d_out;

    static bool attr_set = false;
    if (!attr_set) {
        cudaFuncSetAttribute(gemm_mse_kernel,
                             cudaFuncAttributeMaxDynamicSharedMemorySize,
                             SMEM_BYTES);
        attr_set = true;
    }

    convert_kernel<<<2048, 256>>>(x, W);

    dim3 grid(N_DIM / BM, V_DIM / BN);  // (8, 250): x-fastest -> W stripe L2 reuse
    gemm_mse_kernel<<<grid, THREADS, SMEM_BYTES>>>(y);

    finalize_kernel<<<1, 1>>>(out);
}

// round 6
// speedup vs baseline: 2.7739x; 1.0828x over previous
#include <cuda_runtime.h>
#include <cuda_fp16.h>
#include <cstdint>

#define N_DIM 2048
#define H_DIM 2048
#define V_DIM 32000

// ---- scratch ----
__device__ __half g_Wh[(size_t)V_DIM * H_DIM];   // 131 MB
__device__ __half g_xh[(size_t)N_DIM * H_DIM];   // 8 MB
__device__ double g_acc;

// ============================================================
// Kernel 1: fp32 -> fp16 conversion; zero accumulator
// ============================================================
__global__ void convert_kernel(const float* __restrict__ x,
                               const float* __restrict__ W) {
    size_t tid = (size_t)blockIdx.x * blockDim.x + threadIdx.x;
    size_t stride = (size_t)gridDim.x * blockDim.x;
    if (tid == 0) g_acc = 0.0;

    const size_t nW4 = (size_t)V_DIM * H_DIM / 4;
    const float4* W4 = (const float4*)W;
    for (size_t i = tid; i < nW4; i += stride) {
        float4 v = W4[i];
        __half2* dst = (__half2*)(g_Wh + i * 4);
        dst[0] = __floats2half2_rn(v.x, v.y);
        dst[1] = __floats2half2_rn(v.z, v.w);
    }
    const size_t nx4 = (size_t)N_DIM * H_DIM / 4;
    const float4* x4 = (const float4*)x;
    for (size_t i = tid; i < nx4; i += stride) {
        float4 v = x4[i];
        __half2* dst = (__half2*)(g_xh + i * 4);
        dst[0] = __floats2half2_rn(v.x, v.y);
        dst[1] = __floats2half2_rn(v.z, v.w);
    }
}

// ============================================================
// Kernel 2: fp16 HMMA GEMM (f16 accumulate) + fused (logit-y)^2 reduce
//   CTA tile 256x128, BK=64; 8 warps (4 M x 2 N), warp tile 64x64
//   3-stage cp.async, one __syncthreads per k-tile
// ============================================================
#define BM 256
#define BN 128
#define BK 64
#define NK (H_DIM / BK)               // 32
#define STAGES 3
#define A_BYTES (BM * BK * 2)         // 32768
#define B_BYTES (BN * BK * 2)         // 16384
#define STAGE_BYTES (A_BYTES + B_BYTES)    // 49152
#define SMEM_BYTES (STAGES * STAGE_BYTES)  // 147456
#define THREADS 256

__device__ __forceinline__ void cp_async16(uint32_t smem_addr, const void* gptr) {
    asm volatile("cp.async.cg.shared.global [%0], [%1], 16;"
                 :: "r"(smem_addr), "l"(gptr));
}

__global__ void __launch_bounds__(THREADS)
gemm_mse_kernel(const float* __restrict__ y) {
    extern __shared__ __align__(1024) char smem[];
    __shared__ float red[8];

    const int tid = threadIdx.x;
    const int lane = tid & 31;
    const int warp = tid >> 5;
    const int warp_m = warp & 3;   // 0..3 -> 64-row slabs
    const int warp_n = warp >> 2;  // 0..1 -> 64-col slabs

    const uint32_t sbase = (uint32_t)__cvta_generic_to_shared(smem);

    const int n_blk = blockIdx.x * BM;
    const int v_blk = blockIdx.y * BN;
    const __half* gA = g_xh + (size_t)n_blk * H_DIM;
    const __half* gB = g_Wh + (size_t)v_blk * H_DIM;

    auto issue_tile = [&](int kt) {
        const uint32_t st = sbase + (kt % STAGES) * STAGE_BYTES;
        const __half* gAk = gA + kt * BK;
        const __half* gBk = gB + kt * BK;
        #pragma unroll
        for (int i = 0; i < 8; i++) {
            int chunk = i * THREADS + tid;   // 0..2047
            int row = chunk >> 3;            // 0..255
            int c16 = chunk & 7;
            uint32_t off = (uint32_t)(row * 128 + ((c16 ^ (row & 7)) * 16));
            cp_async16(st + off, gAk + (size_t)row * H_DIM + c16 * 8);
        }
        #pragma unroll
        for (int i = 0; i < 4; i++) {
            int chunk = i * THREADS + tid;   // 0..1023
            int row = chunk >> 3;            // 0..127
            int c16 = chunk & 7;
            uint32_t off = (uint32_t)(row * 128 + ((c16 ^ (row & 7)) * 16));
            cp_async16(st + A_BYTES + off, gBk + (size_t)row * H_DIM + c16 * 8);
        }
    };

    issue_tile(0);
    asm volatile("cp.async.commit_group;");
    issue_tile(1);
    asm volatile("cp.async.commit_group;");

    // f16x2 accumulators: [mi][ni] -> 2 b32 regs (4 halves)
    uint32_t c[4][8][2];
    #pragma unroll
    for (int mi = 0; mi < 4; mi++)
        #pragma unroll
        for (int ni = 0; ni < 8; ni++) {
            c[mi][ni][0] = 0u;
            c[mi][ni][1] = 0u;
        }

    const int a_row_base = warp_m * 64 + (lane & 15);
    const int a_kc_lane = lane >> 4;                  // 0/1
    const int b_row_base = warp_n * 64 + (lane & 7) + ((lane >> 4) << 3);
    const int b_kc_lane = (lane >> 3) & 1;

    for (int kt = 0; kt < NK; kt++) {
        asm volatile("cp.async.wait_group 1;");
        __syncthreads();

        const uint32_t aBase = sbase + (kt % STAGES) * STAGE_BYTES;
        const uint32_t bBase = aBase + A_BYTES;

        #pragma unroll
        for (int ks = 0; ks < 4; ks++) {   // 4 x k16 per tile
            uint32_t a[4][4];
            #pragma unroll
            for (int mi = 0; mi < 4; mi++) {
                int row = a_row_base + mi * 16;
                int kc = ks * 2 + a_kc_lane;
                uint32_t addr = aBase + (uint32_t)(row * 128 + ((kc ^ (row & 7)) * 16));
                asm volatile(
                    "ldmatrix.sync.aligned.m8n8.x4.shared.b16 {%0,%1,%2,%3}, [%4];"
                    : "=r"(a[mi][0]), "=r"(a[mi][1]), "=r"(a[mi][2]), "=r"(a[mi][3])
                    : "r"(addr));
            }
            uint32_t b[4][4];
            #pragma unroll
            for (int p = 0; p < 4; p++) {
                int row = b_row_base + p * 16;
                int kc = ks * 2 + b_kc_lane;
                uint32_t addr = bBase + (uint32_t)(row * 128 + ((kc ^ (row & 7)) * 16));
                asm volatile(
                    "ldmatrix.sync.aligned.m8n8.x4.shared.b16 {%0,%1,%2,%3}, [%4];"
                    : "=r"(b[p][0]), "=r"(b[p][1]), "=r"(b[p][2]), "=r"(b[p][3])
                    : "r"(addr));
            }
            #pragma unroll
            for (int mi = 0; mi < 4; mi++) {
                #pragma unroll
                for (int ni = 0; ni < 8; ni++) {
                    int p = ni >> 1;
                    int o = (ni & 1) * 2;
                    asm volatile(
                        "mma.sync.aligned.m16n8k16.row.col.f16.f16.f16.f16 "
                        "{%0,%1}, {%2,%3,%4,%5}, {%6,%7}, {%0,%1};"
                        : "+r"(c[mi][ni][0]), "+r"(c[mi][ni][1])
                        : "r"(a[mi][0]), "r"(a[mi][1]), "r"(a[mi][2]), "r"(a[mi][3]),
                          "r"(b[p][o]), "r"(b[p][o + 1]));
                }
            }
        }

        if (kt + 2 < NK) issue_tile(kt + 2);
        asm volatile("cp.async.commit_group;");
    }

    // ---- epilogue: (logit - y)^2 ----
    const int gr = lane >> 2;
    const int gc = (lane & 3) * 2;
    float acc = 0.0f;
    #pragma unroll
    for (int mi = 0; mi < 4; mi++) {
        int gn0 = n_blk + warp_m * 64 + mi * 16 + gr;
        const float* y0 = y + (size_t)gn0 * V_DIM + v_blk;
        const float* y8 = y0 + (size_t)8 * V_DIM;
        #pragma unroll
        for (int ni = 0; ni < 8; ni++) {
            int col = warp_n * 64 + ni * 8 + gc;
            float2 y01 = *(const float2*)(y0 + col);
            float2 y23 = *(const float2*)(y8 + col);
            float2 c01 = __half22float2(*(__half2*)&c[mi][ni][0]);
            float2 c23 = __half22float2(*(__half2*)&c[mi][ni][1]);
            float d0 = c01.x - y01.x;
            float d1 = c01.y - y01.y;
            float d2 = c23.x - y23.x;
            float d3 = c23.y - y23.y;
            acc += d0 * d0 + d1 * d1 + d2 * d2 + d3 * d3;
        }
    }
    #pragma unroll
    for (int off = 16; off; off >>= 1)
        acc += __shfl_xor_sync(0xFFFFFFFFu, acc, off);
    if (lane == 0) red[warp] = acc;
    __syncthreads();
    if (warp == 0) {
        float sv = (lane < 8) ? red[lane] : 0.0f;
        #pragma unroll
        for (int off = 4; off; off >>= 1)
            sv += __shfl_xor_sync(0xFFFFFFFFu, sv, off);
        if (lane == 0) atomicAdd(&g_acc, (double)sv);
    }
}

// ============================================================
// Kernel 3: finalize
// ============================================================
__global__ void finalize_kernel(float* out) {
    out[0] = (float)(g_acc / ((double)N_DIM * (double)V_DIM));
}

// ============================================================
extern "C" void kernel_launch(void* const* d_in, const int* in_sizes, int n_in,
                              void* d_out, int out_size) {
    (void)in_sizes; (void)n_in; (void)out_size;
    const float* x = (const float*)d_in[0];   // [N, H]
    const float* y = (const float*)d_in[1];   // [N, V]
    const float* W = (const float*)d_in[2];   // [V, H]
    float* out = (float*)d_out;

    static bool attr_set = false;
    if (!attr_set) {
        cudaFuncSetAttribute(gemm_mse_kernel,
                             cudaFuncAttributeMaxDynamicSharedMemorySize,
                             SMEM_BYTES);
        attr_set = true;
    }

    convert_kernel<<<2048, 256>>>(x, W);

    dim3 grid(N_DIM / BM, V_DIM / BN);  // (8, 250): x-fastest -> W stripe L2 reuse
    gemm_mse_kernel<<<grid, THREADS, SMEM_BYTES>>>(y);

    finalize_kernel<<<1, 1>>>(out);
}